// round 4
// baseline (speedup 1.0000x reference)
#include <cuda_runtime.h>
#include <cstdint>
#include <math.h>

#define E_N      200000
#define A_NUM    8000
#define T_N      1000000
#define NCAT     672
#define EMB_EDGE 512
#define N_TILES  1563
#define NSL0     352
#define NSL1     97

#define OFF_M    0ull
#define OFF_AT   102400000ull
#define OFF_OUT  105600000ull
#define OFF_RE2E 108800000ull
#define OFF_CIR  112000000ull

__device__ float g_radW1[(size_t)E_N * 112];
__device__ float g_hW[2ull * A_NUM * EMB_EDGE];
__device__ float g_WcatT[(size_t)NCAT * 128];

__device__ __forceinline__ float cvt_tf32(float x) {
    uint32_t r;
    asm("cvt.rna.tf32.f32 %0, %1;" : "=r"(r) : "f"(x));
    return __uint_as_float(r);
}

#define MMA8(c, A0, A1, A2, A3, B0, B1) \
    asm("mma.sync.aligned.m16n8k8.row.col.f32.tf32.tf32.f32 " \
        "{%0,%1,%2,%3},{%4,%5,%6,%7},{%8,%9},{%0,%1,%2,%3};" \
        : "+f"((c)[0]), "+f"((c)[1]), "+f"((c)[2]), "+f"((c)[3]) \
        : "r"(__float_as_uint(A0)), "r"(__float_as_uint(A1)), \
          "r"(__float_as_uint(A2)), "r"(__float_as_uint(A3)), \
          "r"(__float_as_uint(B0)), "r"(__float_as_uint(B1)))

// f32x2 helpers (gemm_hw)
__device__ __forceinline__ void ffma2(unsigned long long& d, unsigned long long a,
                                      unsigned long long b) {
    asm("fma.rn.f32x2 %0, %1, %2, %3;" : "=l"(d) : "l"(a), "l"(b), "l"(d));
}
__device__ __forceinline__ unsigned long long pack2(float x, float y) {
    unsigned long long r;
    asm("mov.b64 %0, {%1, %2};" : "=l"(r) : "f"(x), "f"(y));
    return r;
}
union F4U { float4 f; unsigned long long u[2]; };

// ---------------- kernel 1: weights -> g_WcatT [n][k] ----------------
__global__ void build_wcat(const float* __restrict__ Wt, const float* __restrict__ Wc,
                           const float* __restrict__ Wh, const float* __restrict__ Wo,
                           const float* __restrict__ We) {
    int i = blockIdx.x * blockDim.x + threadIdx.x;
    if (i >= NCAT * 128) return;
    int n = i >> 7, r = i & 127;
    float v;
    if (n < 16)        v = Wt[r * 16 + n];
    else if (n < 32)   v = Wh[r * 16 + (n - 16)];
    else if (n < 48)   v = Wo[r * 16 + (n - 32)];
    else if (n < 160)  v = Wc[r * 112 + (n - 48)];
    else               v = We[(size_t)(512 + r) * EMB_EDGE + (n - 160)];
    g_WcatT[(size_t)n * 128 + r] = v;
}

// ---------------- kernel 2: hW = h @ W_edge halves (FFMA2) ----------------
__global__ void __launch_bounds__(256, 2)
gemm_hw(const float* __restrict__ h, const float* __restrict__ We) {
    __shared__ float As[32][132];
    __shared__ float Bs[32][132];
    const int z = blockIdx.z;
    const float* B = We + (size_t)z * 256 * EMB_EDGE;
    float* C = g_hW + (size_t)z * A_NUM * EMB_EDGE;
    const int m0 = blockIdx.y * 128;
    const int n0 = blockIdx.x * 128;
    const int tid = threadIdx.x;
    const int tx = tid & 15, ty = tid >> 4;

    unsigned long long acc[8][4];
#pragma unroll
    for (int i = 0; i < 8; ++i)
#pragma unroll
        for (int j = 0; j < 4; ++j) acc[i][j] = 0ull;

    for (int k0 = 0; k0 < 256; k0 += 32) {
        if (k0) __syncthreads();
#pragma unroll
        for (int i = tid; i < 128 * 32; i += 256) {
            int m = i >> 5, kk = i & 31;
            As[kk][m] = (m0 + m < A_NUM) ? h[(size_t)(m0 + m) * 256 + k0 + kk] : 0.f;
        }
#pragma unroll
        for (int i = tid * 4; i < 32 * 128; i += 1024) {
            int kk = i >> 7, n = i & 127;
            *(float4*)&Bs[kk][n] = *(const float4*)&B[(size_t)(k0 + kk) * EMB_EDGE + n0 + n];
        }
        __syncthreads();
#pragma unroll
        for (int kk = 0; kk < 32; ++kk) {
            float4 a0 = *(const float4*)&As[kk][ty * 8];
            float4 a1 = *(const float4*)&As[kk][ty * 8 + 4];
            F4U b0, b1;
            b0.f = *(const float4*)&Bs[kk][tx * 8];
            b1.f = *(const float4*)&Bs[kk][tx * 8 + 4];
            unsigned long long bb[4] = {b0.u[0], b0.u[1], b1.u[0], b1.u[1]};
            float av[8] = {a0.x, a0.y, a0.z, a0.w, a1.x, a1.y, a1.z, a1.w};
#pragma unroll
            for (int i = 0; i < 8; ++i) {
                unsigned long long a2 = pack2(av[i], av[i]);
#pragma unroll
                for (int j = 0; j < 4; ++j) ffma2(acc[i][j], a2, bb[j]);
            }
        }
    }
#pragma unroll
    for (int i = 0; i < 8; ++i) {
        int m = m0 + ty * 8 + i;
        if (m >= A_NUM) continue;
        float v[8];
#pragma unroll
        for (int j = 0; j < 4; ++j) {
            v[2 * j]     = __uint_as_float((unsigned)(acc[i][j] & 0xffffffffull));
            v[2 * j + 1] = __uint_as_float((unsigned)(acc[i][j] >> 32));
        }
        float* dst = C + (size_t)m * EMB_EDGE + n0 + tx * 8;
        *(float4*)dst       = make_float4(v[0], v[1], v[2], v[3]);
        *(float4*)(dst + 4) = make_float4(v[4], v[5], v[6], v[7]);
    }
}

// ---------------- main GEMM via mma.sync tf32 ----------------
template<int NC, int NPASS>
__device__ __forceinline__ void run_chunk(int colbase, int slice, int nsl,
    const float* __restrict__ dist, const int* __restrict__ eis,
    const int* __restrict__ eit, float* __restrict__ out, float* smem)
{
    constexpr int NFRAG = NC / 16;     // per-warp n fragments
    constexpr int PB = NC + 8;         // 168 or 136, both == 8 mod 32
    float* As = smem;                  // [128 k][136 m]
    float* Bs = smem + 128 * 136;      // [128 k][PB n]
    const int tid = threadIdx.x, wid = tid >> 5, lid = tid & 31;
    const int g = lid >> 2, tc = lid & 3;
    const int m0 = (wid & 3) * 32;
    const int n0 = (wid >> 2) * (NC / 2);

    // ---- fill B panel once ----
    for (int i = tid; i < NC * 128; i += 256) {
        int n = i >> 7, k = i & 127;
        float w = g_WcatT[(size_t)(colbase + n) * 128 + k];
        Bs[k * PB + n] = (NPASS == 1) ? cvt_tf32(w) : w;
    }
    __syncthreads();

    for (int t = slice; t < N_TILES; t += nsl) {
        const int e0 = t * 128;
        // ---- build A tile: rad[e][k], k-major ----
        {
            const int el = tid & 127, dir = tid >> 7, e = e0 + el;
            float f = 0.f, vc = 0.f;
            int r0 = 0;
            if (e < E_N) {
                float ds = dist[e] * (1.0f / 12.0f);
                float ds2 = ds * ds, ds5 = ds2 * ds2 * ds;
                float env = (ds < 1.f) ? (1.f + ds5 * (-21.f + ds * (35.f - 15.f * ds))) : 0.f;
                float u = ds * 127.f;
                r0 = __float2int_rn(u);
                r0 = max(0, min(127, r0));
                f = u - (float)r0;
                vc = env * expf(-0.5f * f * f);
            }
            const float E1 = 0.36787944117144233f;
#define STORE_A(r, v) do { float _v = (v); \
    As[(r) * 136 + el] = (NPASS == 1) ? cvt_tf32(_v) : _v; } while (0)
            if (dir == 0) {
                STORE_A(r0, vc);
                float ratio = __expf(-f - 0.5f), v = vc;
                for (int r = r0 - 1; r >= 0; --r) { v *= ratio; ratio *= E1; STORE_A(r, v); }
            } else {
                float ratio = __expf(f - 0.5f), v = vc;
                for (int r = r0 + 1; r < 128; ++r) { v *= ratio; ratio *= E1; STORE_A(r, v); }
            }
#undef STORE_A
        }
        __syncthreads();

        float acc[2][NFRAG][4];
#pragma unroll
        for (int mf = 0; mf < 2; ++mf)
#pragma unroll
            for (int nf = 0; nf < NFRAG; ++nf)
#pragma unroll
                for (int q = 0; q < 4; ++q) acc[mf][nf][q] = 0.f;

        for (int ks = 0; ks < 16; ++ks) {
            const int kb = ks * 8;
            float ah[2][4], al[2][4];
#pragma unroll
            for (int mf = 0; mf < 2; ++mf) {
                int mr = m0 + mf * 16;
                float a0 = As[(kb + tc) * 136 + mr + g];
                float a1 = As[(kb + tc) * 136 + mr + g + 8];
                float a2 = As[(kb + tc + 4) * 136 + mr + g];
                float a3 = As[(kb + tc + 4) * 136 + mr + g + 8];
                if (NPASS == 3) {
                    ah[mf][0] = cvt_tf32(a0); al[mf][0] = cvt_tf32(a0 - ah[mf][0]);
                    ah[mf][1] = cvt_tf32(a1); al[mf][1] = cvt_tf32(a1 - ah[mf][1]);
                    ah[mf][2] = cvt_tf32(a2); al[mf][2] = cvt_tf32(a2 - ah[mf][2]);
                    ah[mf][3] = cvt_tf32(a3); al[mf][3] = cvt_tf32(a3 - ah[mf][3]);
                } else {
                    ah[mf][0] = a0; ah[mf][1] = a1; ah[mf][2] = a2; ah[mf][3] = a3;
                }
            }
#pragma unroll
            for (int nf = 0; nf < NFRAG; ++nf) {
                int nc = n0 + nf * 8 + g;
                float b0 = Bs[(kb + tc) * PB + nc];
                float b1 = Bs[(kb + tc + 4) * PB + nc];
                if (NPASS == 3) {
                    float bh0 = cvt_tf32(b0), bl0 = cvt_tf32(b0 - bh0);
                    float bh1 = cvt_tf32(b1), bl1 = cvt_tf32(b1 - bh1);
#pragma unroll
                    for (int mf = 0; mf < 2; ++mf) {
                        MMA8(acc[mf][nf], ah[mf][0], ah[mf][1], ah[mf][2], ah[mf][3], bh0, bh1);
                        MMA8(acc[mf][nf], ah[mf][0], ah[mf][1], ah[mf][2], ah[mf][3], bl0, bl1);
                        MMA8(acc[mf][nf], al[mf][0], al[mf][1], al[mf][2], al[mf][3], bh0, bh1);
                    }
                } else {
#pragma unroll
                    for (int mf = 0; mf < 2; ++mf)
                        MMA8(acc[mf][nf], ah[mf][0], ah[mf][1], ah[mf][2], ah[mf][3], b0, b1);
                }
            }
        }
        __syncthreads();   // all warps done reading As before next rebuild

        // ---- epilogue ----
#pragma unroll
        for (int mf = 0; mf < 2; ++mf)
#pragma unroll
            for (int half = 0; half < 2; ++half) {
                int e2 = e0 + m0 + mf * 16 + g + half * 8;
                if (e2 >= E_N) continue;
                if (NPASS == 1) {
                    const int mbase = colbase - 160;
                    int si = eis[e2], ti = eit[e2];
                    const float* hw1 = g_hW + (size_t)si * EMB_EDGE;
                    const float* hw2 = g_hW + (size_t)A_NUM * EMB_EDGE + (size_t)ti * EMB_EDGE;
                    float* dstm = out + OFF_M + (size_t)e2 * EMB_EDGE;
#pragma unroll
                    for (int nf = 0; nf < NFRAG; ++nf) {
                        int mc = mbase + n0 + nf * 8 + 2 * tc;
                        float2 a = *(const float2*)(hw1 + mc);
                        float2 b = *(const float2*)(hw2 + mc);
                        float x0 = acc[mf][nf][half * 2]     + a.x + b.x;
                        float x1 = acc[mf][nf][half * 2 + 1] + a.y + b.y;
                        float2 o;
                        o.x = x0 * (1.0f / 0.6f) / (1.0f + __expf(-x0));
                        o.y = x1 * (1.0f / 0.6f) / (1.0f + __expf(-x1));
                        *(float2*)(dstm + mc) = o;
                    }
                } else {
#pragma unroll
                    for (int nf = 0; nf < NFRAG; ++nf) {
                        int gcol = n0 + nf * 8 + 2 * tc;
                        float2 v = make_float2(acc[mf][nf][half * 2],
                                               acc[mf][nf][half * 2 + 1]);
                        float* dst;
                        if (gcol < 48) {
                            size_t base = (gcol < 16) ? OFF_RE2E : (gcol < 32) ? OFF_AT : OFF_OUT;
                            dst = out + base + (size_t)e2 * 16 + (gcol & 15);
                        } else {
                            dst = g_radW1 + (size_t)e2 * 112 + (gcol - 48);
                        }
                        *(float2*)dst = v;
                    }
                }
            }
    }
}

__global__ void __launch_bounds__(256, 1)
main_mma(const float* __restrict__ dist, const int* __restrict__ eis,
         const int* __restrict__ eit, float* __restrict__ out) {
    extern __shared__ float smem[];
    int bx = blockIdx.x;
    if (bx < NSL0) {
        run_chunk<160, 3>(0, bx, NSL0, dist, eis, eit, out, smem);
    } else {
        int r = bx - NSL0;
        int ci = r / NSL1;
        run_chunk<128, 1>(160 + 128 * ci, r % NSL1, NSL1, dist, eis, eit, out, smem);
    }
}

// ---------------- kernel 4: triplets ----------------
__global__ void __launch_bounds__(256)
trip_kernel(const int* __restrict__ tin, const int* __restrict__ tout,
            const float* __restrict__ vec, float* __restrict__ out) {
    int gidx = blockIdx.x * blockDim.x + threadIdx.x;
    int t = gidx >> 4;
    int c = gidx & 15;
    if (t >= T_N) return;
    int lane = threadIdx.x & 31;

    int i_out = 0;
    float cosv = 0.f;
    if ((lane & 15) == 0) {
        int i_in = tin[t];
        i_out = tout[t];
        float ax = vec[3 * (size_t)i_out + 0], ay = vec[3 * (size_t)i_out + 1],
              az = vec[3 * (size_t)i_out + 2];
        float bx = vec[3 * (size_t)i_in + 0], by = vec[3 * (size_t)i_in + 1],
              bz = vec[3 * (size_t)i_in + 2];
        cosv = ax * bx + ay * by + az * bz;
        cosv = fminf(1.f, fmaxf(-1.f, cosv));
    }
    const unsigned mask = 0xffffffffu;
    i_out = __shfl_sync(mask, i_out, lane & 16, 32);
    cosv  = __shfl_sync(mask, cosv, lane & 16, 32);

    const float* row = g_radW1 + (size_t)i_out * 112 + c;
    float x = cosv;
    float P0 = 1.f, P1 = x;
    float P2 = (3.f * x * P1 - 1.f * P0) * (1.f / 2.f);
    float P3 = (5.f * x * P2 - 2.f * P1) * (1.f / 3.f);
    float P4 = (7.f * x * P3 - 3.f * P2) * (1.f / 4.f);
    float P5 = (9.f * x * P4 - 4.f * P3) * (1.f / 5.f);
    float P6 = (11.f * x * P5 - 5.f * P4) * (1.f / 6.f);

    float acc;
    acc  = 0.28209479177387814f * P0 * row[0];
    acc += 0.4886025119029199f  * P1 * row[16];
    acc += 0.6307831305050401f  * P2 * row[32];
    acc += 0.7463526651802308f  * P3 * row[48];
    acc += 0.8462843753216345f  * P4 * row[64];
    acc += 0.9356025796273889f  * P5 * row[80];
    acc += 1.0171072362820548f  * P6 * row[96];

    out[OFF_CIR + (size_t)t * 16 + c] = acc;
}

// ---------------- launch ----------------
extern "C" void kernel_launch(void* const* d_in, const int* in_sizes, int n_in,
                              void* d_out, int out_size) {
    const float* h    = (const float*)d_in[0];
    const float* dist = (const float*)d_in[1];
    const float* vec  = (const float*)d_in[2];
    const int*   eis  = (const int*)d_in[3];
    const int*   eit  = (const int*)d_in[4];
    const int*   tin  = (const int*)d_in[5];
    const int*   tout = (const int*)d_in[6];
    const float* Wt   = (const float*)d_in[7];
    const float* Wc   = (const float*)d_in[8];
    const float* Wh   = (const float*)d_in[9];
    const float* Wo   = (const float*)d_in[10];
    const float* We   = (const float*)d_in[11];
    float* out = (float*)d_out;

    const int MAIN_SMEM = (128 * 136 + 128 * 168) * 4;  // 155648 B
    cudaFuncSetAttribute(main_mma, cudaFuncAttributeMaxDynamicSharedMemorySize, MAIN_SMEM);

    build_wcat<<<(NCAT * 128 + 255) / 256, 256>>>(Wt, Wc, Wh, Wo, We);
    gemm_hw<<<dim3(4, (A_NUM + 127) / 128, 2), 256>>>(h, We);
    main_mma<<<NSL0 + 4 * NSL1, 256, MAIN_SMEM>>>(dist, eis, eit, out);
    trip_kernel<<<(T_N * 16) / 256, 256>>>(tin, tout, vec, out);
}

// round 5
// speedup vs baseline: 1.6703x; 1.6703x over previous
#include <cuda_runtime.h>
#include <cstdint>
#include <math.h>

#define E_N      200000
#define A_NUM    8000
#define T_N      1000000
#define NCAT     672
#define EMB_EDGE 512
#define N_TILES  1563
#define NSL      261          // edge-tile slices; grid = 6*NSL

#define OFF_M    0ull
#define OFF_AT   102400000ull
#define OFF_OUT  105600000ull
#define OFF_RE2E 108800000ull
#define OFF_CIR  112000000ull

__device__ float g_radW1[(size_t)E_N * 112];
__device__ float g_hW[2ull * A_NUM * EMB_EDGE];
__device__ float g_Wcat[128 * NCAT];            // [k][n]
__device__ int   g_cnt[128];
__device__ int   g_order[N_TILES * 128];

// ---------------- helpers ----------------
__device__ __forceinline__ void ffma2(unsigned long long& d, unsigned long long a,
                                      unsigned long long b) {
    asm("fma.rn.f32x2 %0, %1, %2, %3;" : "=l"(d) : "l"(a), "l"(b), "l"(d));
}
__device__ __forceinline__ unsigned long long pack2(float x, float y) {
    unsigned long long r;
    asm("mov.b64 %0, {%1, %2};" : "=l"(r) : "f"(x), "f"(y));
    return r;
}
union F4U { float4 f; unsigned long long u[2]; };

__device__ __forceinline__ int edge_r0(float d) {
    float u = d * (127.0f / 12.0f);
    int r0 = __float2int_rn(u);
    return max(0, min(127, r0));
}

// ---------------- sort kernels ----------------
__global__ void k_clear() {
    int tid = threadIdx.x;
    if (tid < 128) g_cnt[tid] = 0;
    if (tid < 64) g_order[E_N + tid] = -1;   // pad last tile
}
__global__ void k_hist(const float* __restrict__ dist) {
    int e = blockIdx.x * blockDim.x + threadIdx.x;
    if (e >= E_N) return;
    atomicAdd(&g_cnt[edge_r0(dist[e])], 1);
}
__global__ void k_scan() {   // single block of 128: exclusive prefix in place
    __shared__ int s[128];
    int tid = threadIdx.x;
    int v = g_cnt[tid];
    s[tid] = v;
    __syncthreads();
    int sum = 0;
    for (int i = 0; i < 128; ++i) {          // cheap; done by thread 0
        if (tid == 0) { int c = s[i]; s[i] = sum; sum += c; }
    }
    __syncthreads();
    g_cnt[tid] = s[tid];
}
__global__ void k_scatter(const float* __restrict__ dist) {
    int e = blockIdx.x * blockDim.x + threadIdx.x;
    if (e >= E_N) return;
    int p = atomicAdd(&g_cnt[edge_r0(dist[e])], 1);
    g_order[p] = e;
}

// ---------------- weights -> g_Wcat [k][n] ----------------
__global__ void build_wcat(const float* __restrict__ Wt, const float* __restrict__ Wc,
                           const float* __restrict__ Wh, const float* __restrict__ Wo,
                           const float* __restrict__ We) {
    int i = blockIdx.x * blockDim.x + threadIdx.x;
    if (i >= 128 * NCAT) return;
    int k = i / NCAT, n = i - k * NCAT;
    float v;
    if (n < 16)        v = Wt[k * 16 + n];
    else if (n < 32)   v = Wh[k * 16 + (n - 16)];
    else if (n < 48)   v = Wo[k * 16 + (n - 32)];
    else if (n < 160)  v = Wc[k * 112 + (n - 48)];
    else               v = We[(size_t)(512 + k) * EMB_EDGE + (n - 160)];
    g_Wcat[i] = v;
}

// ---------------- hW = h @ W_edge halves (FFMA2) ----------------
__global__ void __launch_bounds__(256, 2)
gemm_hw(const float* __restrict__ h, const float* __restrict__ We) {
    __shared__ float As[32][132];
    __shared__ float Bs[32][132];
    const int z = blockIdx.z;
    const float* B = We + (size_t)z * 256 * EMB_EDGE;
    float* C = g_hW + (size_t)z * A_NUM * EMB_EDGE;
    const int m0 = blockIdx.y * 128;
    const int n0 = blockIdx.x * 128;
    const int tid = threadIdx.x;
    const int tx = tid & 15, ty = tid >> 4;

    unsigned long long acc[8][4];
#pragma unroll
    for (int i = 0; i < 8; ++i)
#pragma unroll
        for (int j = 0; j < 4; ++j) acc[i][j] = 0ull;

    for (int k0 = 0; k0 < 256; k0 += 32) {
        if (k0) __syncthreads();
#pragma unroll
        for (int i = tid; i < 128 * 32; i += 256) {
            int m = i >> 5, kk = i & 31;
            As[kk][m] = (m0 + m < A_NUM) ? h[(size_t)(m0 + m) * 256 + k0 + kk] : 0.f;
        }
#pragma unroll
        for (int i = tid * 4; i < 32 * 128; i += 1024) {
            int kk = i >> 7, n = i & 127;
            *(float4*)&Bs[kk][n] = *(const float4*)&B[(size_t)(k0 + kk) * EMB_EDGE + n0 + n];
        }
        __syncthreads();
#pragma unroll
        for (int kk = 0; kk < 32; ++kk) {
            float4 a0 = *(const float4*)&As[kk][ty * 8];
            float4 a1 = *(const float4*)&As[kk][ty * 8 + 4];
            F4U b0, b1;
            b0.f = *(const float4*)&Bs[kk][tx * 8];
            b1.f = *(const float4*)&Bs[kk][tx * 8 + 4];
            unsigned long long bb[4] = {b0.u[0], b0.u[1], b1.u[0], b1.u[1]};
            float av[8] = {a0.x, a0.y, a0.z, a0.w, a1.x, a1.y, a1.z, a1.w};
#pragma unroll
            for (int i = 0; i < 8; ++i) {
                unsigned long long a2 = pack2(av[i], av[i]);
#pragma unroll
                for (int j = 0; j < 4; ++j) ffma2(acc[i][j], a2, bb[j]);
            }
        }
    }
#pragma unroll
    for (int i = 0; i < 8; ++i) {
        int m = m0 + ty * 8 + i;
        if (m >= A_NUM) continue;
        float v[8];
#pragma unroll
        for (int j = 0; j < 4; ++j) {
            v[2 * j]     = __uint_as_float((unsigned)(acc[i][j] & 0xffffffffull));
            v[2 * j + 1] = __uint_as_float((unsigned)(acc[i][j] >> 32));
        }
        float* dst = C + (size_t)m * EMB_EDGE + n0 + tx * 8;
        *(float4*)dst       = make_float4(v[0], v[1], v[2], v[3]);
        *(float4*)(dst + 4) = make_float4(v[4], v[5], v[6], v[7]);
    }
}

// ---------------- main: banded rad @ Wcat over sorted edges ----------------
__global__ void __launch_bounds__(256)
main_band(const float* __restrict__ dist, const int* __restrict__ eis,
          const int* __restrict__ eit, float* __restrict__ out) {
    __shared__ float As[16][132];
    __shared__ float Bs[16][132];
    __shared__ int s_red[4];
    __shared__ int s_kmin;

    const int ci = blockIdx.x % 6;
    const int slice = blockIdx.x / 6;
    const int n0 = ci * 128;
    const int tid = threadIdx.x;
    const int tx = tid & 15, ty = tid >> 4;

    for (int t = slice; t < N_TILES; t += NSL) {
        const int e0 = t * 128;

        // ---- per-edge params (threads 0..127) + tile min(r0) ----
        int id = -1, r0v = 10000;
        float f = 0.f, vc = 0.f;
        if (tid < 128) {
            id = g_order[e0 + tid];
            if (id >= 0) {
                float ds = dist[id] * (1.0f / 12.0f);
                float ds2 = ds * ds, ds5 = ds2 * ds2 * ds;
                float env = (ds < 1.f) ? (1.f + ds5 * (-21.f + ds * (35.f - 15.f * ds))) : 0.f;
                float u = ds * 127.f;
                r0v = __float2int_rn(u);
                r0v = max(0, min(127, r0v));
                f = u - (float)r0v;
                vc = env * expf(-0.5f * f * f);
            }
        }
        int mn = r0v;
#pragma unroll
        for (int o = 16; o > 0; o >>= 1) mn = min(mn, __shfl_xor_sync(0xffffffffu, mn, o));
        if (tid < 128 && (tid & 31) == 0) s_red[tid >> 5] = mn;
        __syncthreads();
        if (tid == 0)
            s_kmin = max(0, min(min(s_red[0], s_red[1]), min(s_red[2], s_red[3])) - 5);
        // ---- zero A ----
        {
            float* Af = &As[0][0];
            for (int i = tid; i < 16 * 132; i += 256) Af[i] = 0.f;
        }
        __syncthreads();
        const int kmin = s_kmin;

        // ---- scatter taps (11 per edge) ----
        if (tid < 128 && id >= 0) {
            const float E1 = 0.36787944117144233f;
            const int el = tid;
            {
                int rel = r0v - kmin;
                if (rel < 16) As[rel][el] = vc;
            }
            float ratio = __expf(-f - 0.5f), v = vc;
#pragma unroll
            for (int j = 1; j <= 5; ++j) {
                v *= ratio; ratio *= E1;
                int r = r0v - j;
                if (r >= 0) { int rel = r - kmin; if (rel >= 0 && rel < 16) As[rel][el] = v; }
            }
            ratio = __expf(f - 0.5f); v = vc;
#pragma unroll
            for (int j = 1; j <= 5; ++j) {
                v *= ratio; ratio *= E1;
                int r = r0v + j;
                if (r < 128) { int rel = r - kmin; if (rel < 16) As[rel][el] = v; }
            }
        }
        // ---- fill B slice (16 k-rows x 128 cols) ----
        for (int i = tid * 4; i < 16 * 128; i += 1024) {
            int k = i >> 7, n = i & 127;
            int gk = kmin + k, gn = n0 + n;
            float4 w = make_float4(0.f, 0.f, 0.f, 0.f);
            if (gk < 128 && gn < NCAT) w = *(const float4*)&g_Wcat[gk * NCAT + gn];
            *(float4*)&Bs[k][n] = w;
        }
        __syncthreads();

        // ---- 16-step k-loop ----
        unsigned long long acc[8][4];
#pragma unroll
        for (int i = 0; i < 8; ++i)
#pragma unroll
            for (int j = 0; j < 4; ++j) acc[i][j] = 0ull;
#pragma unroll
        for (int kk = 0; kk < 16; ++kk) {
            float4 a0 = *(const float4*)&As[kk][ty * 8];
            float4 a1 = *(const float4*)&As[kk][ty * 8 + 4];
            F4U b0, b1;
            b0.f = *(const float4*)&Bs[kk][tx * 8];
            b1.f = *(const float4*)&Bs[kk][tx * 8 + 4];
            unsigned long long bb[4] = {b0.u[0], b0.u[1], b1.u[0], b1.u[1]};
            float av[8] = {a0.x, a0.y, a0.z, a0.w, a1.x, a1.y, a1.z, a1.w};
#pragma unroll
            for (int i = 0; i < 8; ++i) {
                unsigned long long a2 = pack2(av[i], av[i]);
#pragma unroll
                for (int j = 0; j < 4; ++j) ffma2(acc[i][j], a2, bb[j]);
            }
        }

        // ---- epilogue (route columns; scatter rows by original edge id) ----
        const int nb = n0 + tx * 8;
        if (nb < NCAT) {
#pragma unroll
            for (int i = 0; i < 8; ++i) {
                int id2 = g_order[e0 + ty * 8 + i];
                if (id2 < 0) continue;
                float v[8];
#pragma unroll
                for (int j = 0; j < 4; ++j) {
                    v[2 * j]     = __uint_as_float((unsigned)(acc[i][j] & 0xffffffffull));
                    v[2 * j + 1] = __uint_as_float((unsigned)(acc[i][j] >> 32));
                }
                if (nb >= 160) {
                    int j2 = nb - 160;
                    int si = eis[id2], ti = eit[id2];
                    const float* hw1 = g_hW + (size_t)si * EMB_EDGE + j2;
                    const float* hw2 = g_hW + (size_t)A_NUM * EMB_EDGE
                                       + (size_t)ti * EMB_EDGE + j2;
                    float4 p1a = *(const float4*)hw1, p1b = *(const float4*)(hw1 + 4);
                    float4 p2a = *(const float4*)hw2, p2b = *(const float4*)(hw2 + 4);
                    float add[8] = {p1a.x + p2a.x, p1a.y + p2a.y, p1a.z + p2a.z,
                                    p1a.w + p2a.w, p1b.x + p2b.x, p1b.y + p2b.y,
                                    p1b.z + p2b.z, p1b.w + p2b.w};
                    float r[8];
#pragma unroll
                    for (int j = 0; j < 8; ++j) {
                        float x = v[j] + add[j];
                        r[j] = x * (1.0f / 0.6f) / (1.0f + __expf(-x));
                    }
                    float* dst = out + OFF_M + (size_t)id2 * EMB_EDGE + j2;
                    *(float4*)dst       = make_float4(r[0], r[1], r[2], r[3]);
                    *(float4*)(dst + 4) = make_float4(r[4], r[5], r[6], r[7]);
                } else if (nb >= 48) {
                    float* dst = g_radW1 + (size_t)id2 * 112 + (nb - 48);
                    *(float4*)dst       = make_float4(v[0], v[1], v[2], v[3]);
                    *(float4*)(dst + 4) = make_float4(v[4], v[5], v[6], v[7]);
                } else {
                    int seg = nb >> 4;
                    size_t base = (seg == 0) ? OFF_RE2E : (seg == 1) ? OFF_AT : OFF_OUT;
                    float* dst = out + base + (size_t)id2 * 16 + (nb & 15);
                    *(float4*)dst       = make_float4(v[0], v[1], v[2], v[3]);
                    *(float4*)(dst + 4) = make_float4(v[4], v[5], v[6], v[7]);
                }
            }
        }
        __syncthreads();
    }
}

// ---------------- triplets ----------------
__global__ void __launch_bounds__(256)
trip_kernel(const int* __restrict__ tin, const int* __restrict__ tout,
            const float* __restrict__ vec, float* __restrict__ out) {
    int gidx = blockIdx.x * blockDim.x + threadIdx.x;
    int t = gidx >> 4;
    int c = gidx & 15;
    if (t >= T_N) return;
    int lane = threadIdx.x & 31;

    int i_out = 0;
    float cosv = 0.f;
    if ((lane & 15) == 0) {
        int i_in = tin[t];
        i_out = tout[t];
        float ax = vec[3 * (size_t)i_out + 0], ay = vec[3 * (size_t)i_out + 1],
              az = vec[3 * (size_t)i_out + 2];
        float bx = vec[3 * (size_t)i_in + 0], by = vec[3 * (size_t)i_in + 1],
              bz = vec[3 * (size_t)i_in + 2];
        cosv = ax * bx + ay * by + az * bz;
        cosv = fminf(1.f, fmaxf(-1.f, cosv));
    }
    const unsigned mask = 0xffffffffu;
    i_out = __shfl_sync(mask, i_out, lane & 16, 32);
    cosv  = __shfl_sync(mask, cosv, lane & 16, 32);

    const float* row = g_radW1 + (size_t)i_out * 112 + c;
    float x = cosv;
    float P0 = 1.f, P1 = x;
    float P2 = (3.f * x * P1 - 1.f * P0) * (1.f / 2.f);
    float P3 = (5.f * x * P2 - 2.f * P1) * (1.f / 3.f);
    float P4 = (7.f * x * P3 - 3.f * P2) * (1.f / 4.f);
    float P5 = (9.f * x * P4 - 4.f * P3) * (1.f / 5.f);
    float P6 = (11.f * x * P5 - 5.f * P4) * (1.f / 6.f);

    float acc;
    acc  = 0.28209479177387814f * P0 * row[0];
    acc += 0.4886025119029199f  * P1 * row[16];
    acc += 0.6307831305050401f  * P2 * row[32];
    acc += 0.7463526651802308f  * P3 * row[48];
    acc += 0.8462843753216345f  * P4 * row[64];
    acc += 0.9356025796273889f  * P5 * row[80];
    acc += 1.0171072362820548f  * P6 * row[96];

    out[OFF_CIR + (size_t)t * 16 + c] = acc;
}

// ---------------- launch ----------------
extern "C" void kernel_launch(void* const* d_in, const int* in_sizes, int n_in,
                              void* d_out, int out_size) {
    const float* h    = (const float*)d_in[0];
    const float* dist = (const float*)d_in[1];
    const float* vec  = (const float*)d_in[2];
    const int*   eis  = (const int*)d_in[3];
    const int*   eit  = (const int*)d_in[4];
    const int*   tin  = (const int*)d_in[5];
    const int*   tout = (const int*)d_in[6];
    const float* Wt   = (const float*)d_in[7];
    const float* Wc   = (const float*)d_in[8];
    const float* Wh   = (const float*)d_in[9];
    const float* Wo   = (const float*)d_in[10];
    const float* We   = (const float*)d_in[11];
    float* out = (float*)d_out;

    k_clear<<<1, 256>>>();
    k_hist<<<(E_N + 255) / 256, 256>>>(dist);
    k_scan<<<1, 128>>>();
    k_scatter<<<(E_N + 255) / 256, 256>>>(dist);
    build_wcat<<<(128 * NCAT + 255) / 256, 256>>>(Wt, Wc, Wh, Wo, We);
    gemm_hw<<<dim3(4, (A_NUM + 127) / 128, 2), 256>>>(h, We);
    main_band<<<6 * NSL, 256>>>(dist, eis, eit, out);
    trip_kernel<<<(T_N * 16) / 256, 256>>>(tin, tout, vec, out);
}

// round 6
// speedup vs baseline: 1.8349x; 1.0985x over previous
#include <cuda_runtime.h>
#include <cstdint>
#include <math.h>

#define E_N      200000
#define A_NUM    8000
#define T_N      1000000
#define NCAT     672
#define EMB_EDGE 512
#define N_TILES  1563
#define NSL      261          // edge-tile slices; main grid = 6*NSL

#define OFF_M    0ull
#define OFF_AT   102400000ull
#define OFF_OUT  105600000ull
#define OFF_RE2E 108800000ull
#define OFF_CIR  112000000ull

#define GEMM_BLKS 504         // 4 x 63 x 2
#define HIST_BLKS 128

__device__ float g_radW1[(size_t)E_N * 112];
__device__ float g_hW[2ull * A_NUM * EMB_EDGE];
__device__ float g_Wcat[128 * NCAT];            // [k][n]
__device__ int   g_cnt[128];
__device__ int   g_pos[128];
__device__ int   g_done;
__device__ int   g_order[N_TILES * 128];

// ---------------- helpers ----------------
__device__ __forceinline__ void ffma2(unsigned long long& d, unsigned long long a,
                                      unsigned long long b) {
    asm("fma.rn.f32x2 %0, %1, %2, %3;" : "=l"(d) : "l"(a), "l"(b), "l"(d));
}
__device__ __forceinline__ unsigned long long pack2(float x, float y) {
    unsigned long long r;
    asm("mov.b64 %0, {%1, %2};" : "=l"(r) : "f"(x), "f"(y));
    return r;
}
union F4U { float4 f; unsigned long long u[2]; };

__device__ __forceinline__ int edge_r0(float d) {
    float u = d * (127.0f / 12.0f);
    int r0 = __float2int_rn(u);
    return max(0, min(127, r0));
}

// ---------------- kernel 0: init + build wcat ----------------
__global__ void k_init(const float* __restrict__ Wt, const float* __restrict__ Wc,
                       const float* __restrict__ Wh, const float* __restrict__ Wo,
                       const float* __restrict__ We) {
    int i = blockIdx.x * blockDim.x + threadIdx.x;
    if (blockIdx.x == 0) {
        int tid = threadIdx.x;
        if (tid < 128) { g_cnt[tid] = 0; g_pos[tid] = 0; }
        if (tid == 128) g_done = 0;
        if (tid >= 129 && tid < 129 + (N_TILES * 128 - E_N))
            g_order[E_N + tid - 129] = -1;
    }
    if (i >= 128 * NCAT) return;
    int k = i / NCAT, n = i - k * NCAT;
    float v;
    if (n < 16)        v = Wt[k * 16 + n];
    else if (n < 32)   v = Wh[k * 16 + (n - 16)];
    else if (n < 48)   v = Wo[k * 16 + (n - 32)];
    else if (n < 160)  v = Wc[k * 112 + (n - 48)];
    else               v = We[(size_t)(512 + k) * EMB_EDGE + (n - 160)];
    g_Wcat[i] = v;
}

// ---------------- kernel 1: gemm_hw (blocks <504) + hist/scan (blocks >=504) ----
__global__ void __launch_bounds__(256, 2)
k_gemm_hist(const float* __restrict__ h, const float* __restrict__ We,
            const float* __restrict__ dist) {
    __shared__ float As[32][132];
    __shared__ float Bs[32][132];

    if (blockIdx.x >= GEMM_BLKS) {
        // -------- histogram path --------
        __shared__ int scnt[128];
        __shared__ int sv[128];
        __shared__ int sdone;
        const int hb = blockIdx.x - GEMM_BLKS;
        const int tid = threadIdx.x;
        if (tid < 128) scnt[tid] = 0;
        __syncthreads();
        for (int e = hb * 256 + tid; e < E_N; e += HIST_BLKS * 256)
            atomicAdd(&scnt[edge_r0(dist[e])], 1);
        __syncthreads();
        if (tid < 128 && scnt[tid] > 0) atomicAdd(&g_cnt[tid], scnt[tid]);
        __threadfence();
        if (tid == 0) {
            int o = atomicAdd(&g_done, 1);
            sdone = (o == HIST_BLKS - 1) ? 1 : 0;
        }
        __syncthreads();
        if (!sdone) return;
        // last block: exclusive scan of g_cnt -> g_pos
        int c0 = 0;
        if (tid < 128) { c0 = *((volatile int*)&g_cnt[tid]); sv[tid] = c0; }
        __syncthreads();
        for (int o = 1; o < 128; o <<= 1) {
            int v = 0;
            if (tid < 128 && tid >= o) v = sv[tid - o];
            __syncthreads();
            if (tid < 128) sv[tid] += v;
            __syncthreads();
        }
        if (tid < 128) g_pos[tid] = sv[tid] - c0;
        return;
    }

    // -------- gemm path --------
    const int bx = blockIdx.x;
    const int z = bx / 252;
    const int rem = bx % 252;
    const int by = rem / 4;
    const int bnx = rem % 4;
    const float* B = We + (size_t)z * 256 * EMB_EDGE;
    float* C = g_hW + (size_t)z * A_NUM * EMB_EDGE;
    const int m0 = by * 128;
    const int n0 = bnx * 128;
    const int tid = threadIdx.x;
    const int tx = tid & 15, ty = tid >> 4;

    unsigned long long acc[8][4];
#pragma unroll
    for (int i = 0; i < 8; ++i)
#pragma unroll
        for (int j = 0; j < 4; ++j) acc[i][j] = 0ull;

    for (int k0 = 0; k0 < 256; k0 += 32) {
        if (k0) __syncthreads();
#pragma unroll
        for (int i = tid; i < 128 * 32; i += 256) {
            int m = i >> 5, kk = i & 31;
            As[kk][m] = (m0 + m < A_NUM) ? h[(size_t)(m0 + m) * 256 + k0 + kk] : 0.f;
        }
#pragma unroll
        for (int i = tid * 4; i < 32 * 128; i += 1024) {
            int kk = i >> 7, n = i & 127;
            *(float4*)&Bs[kk][n] = *(const float4*)&B[(size_t)(k0 + kk) * EMB_EDGE + n0 + n];
        }
        __syncthreads();
#pragma unroll
        for (int kk = 0; kk < 32; ++kk) {
            float4 a0 = *(const float4*)&As[kk][ty * 8];
            float4 a1 = *(const float4*)&As[kk][ty * 8 + 4];
            F4U b0, b1;
            b0.f = *(const float4*)&Bs[kk][tx * 8];
            b1.f = *(const float4*)&Bs[kk][tx * 8 + 4];
            unsigned long long bb[4] = {b0.u[0], b0.u[1], b1.u[0], b1.u[1]};
            float av[8] = {a0.x, a0.y, a0.z, a0.w, a1.x, a1.y, a1.z, a1.w};
#pragma unroll
            for (int i = 0; i < 8; ++i) {
                unsigned long long a2 = pack2(av[i], av[i]);
#pragma unroll
                for (int j = 0; j < 4; ++j) ffma2(acc[i][j], a2, bb[j]);
            }
        }
    }
#pragma unroll
    for (int i = 0; i < 8; ++i) {
        int m = m0 + ty * 8 + i;
        if (m >= A_NUM) continue;
        float v[8];
#pragma unroll
        for (int j = 0; j < 4; ++j) {
            v[2 * j]     = __uint_as_float((unsigned)(acc[i][j] & 0xffffffffull));
            v[2 * j + 1] = __uint_as_float((unsigned)(acc[i][j] >> 32));
        }
        float* dst = C + (size_t)m * EMB_EDGE + n0 + tx * 8;
        *(float4*)dst       = make_float4(v[0], v[1], v[2], v[3]);
        *(float4*)(dst + 4) = make_float4(v[4], v[5], v[6], v[7]);
    }
}

// ---------------- kernel 2: scatter (block = 1024 edges, smem-aggregated) ----
__global__ void __launch_bounds__(256)
k_scatter(const float* __restrict__ dist) {
    __shared__ int scnt[128];
    __shared__ int sbase[128];
    const int tid = threadIdx.x;
    const int base = blockIdx.x * 1024;
    if (tid < 128) scnt[tid] = 0;
    __syncthreads();
    int r0[4], lp[4];
#pragma unroll
    for (int j = 0; j < 4; ++j) {
        int e = base + j * 256 + tid;
        r0[j] = -1;
        if (e < E_N) { r0[j] = edge_r0(dist[e]); lp[j] = atomicAdd(&scnt[r0[j]], 1); }
    }
    __syncthreads();
    if (tid < 128 && scnt[tid] > 0) sbase[tid] = atomicAdd(&g_pos[tid], scnt[tid]);
    __syncthreads();
#pragma unroll
    for (int j = 0; j < 4; ++j) {
        int e = base + j * 256 + tid;
        if (e < E_N) g_order[sbase[r0[j]] + lp[j]] = e;
    }
}

// ---------------- kernel 3: banded rad @ Wcat over sorted edges ----------------
__global__ void __launch_bounds__(256)
main_band(const float* __restrict__ dist, const int* __restrict__ eis,
          const int* __restrict__ eit, float* __restrict__ out) {
    __shared__ float As[16][132];
    __shared__ float Bs[16][132];
    __shared__ int s_red[8];
    __shared__ int s_kmin;

    const int ci = blockIdx.x % 6;
    const int slice = blockIdx.x / 6;
    const int n0 = ci * 128;
    const int tid = threadIdx.x;
    const int tx = tid & 15, ty = tid >> 4;
    const int el = tid & 127, dir = tid >> 7;

    for (int t = slice; t < N_TILES; t += NSL) {
        const int e0 = t * 128;

        // ---- per-edge params (all 256 threads; dup per edge) + tile min(r0) ----
        int id = g_order[e0 + el];
        int r0v = 10000;
        float f = 0.f, vc = 0.f;
        if (id >= 0) {
            float ds = dist[id] * (1.0f / 12.0f);
            float ds2 = ds * ds, ds5 = ds2 * ds2 * ds;
            float env = (ds < 1.f) ? (1.f + ds5 * (-21.f + ds * (35.f - 15.f * ds))) : 0.f;
            float u = ds * 127.f;
            r0v = __float2int_rn(u);
            r0v = max(0, min(127, r0v));
            f = u - (float)r0v;
            vc = env * expf(-0.5f * f * f);
        }
        int mn = r0v;
#pragma unroll
        for (int o = 16; o > 0; o >>= 1) mn = min(mn, __shfl_xor_sync(0xffffffffu, mn, o));
        if ((tid & 31) == 0) s_red[tid >> 5] = mn;
        __syncthreads();
        if (tid == 0) {
            int m2 = min(min(min(s_red[0], s_red[1]), min(s_red[2], s_red[3])),
                         min(min(s_red[4], s_red[5]), min(s_red[6], s_red[7])));
            s_kmin = max(0, m2 - 5);
        }
        // ---- zero A ----
        {
            float* Af = &As[0][0];
            for (int i = tid; i < 16 * 132; i += 256) Af[i] = 0.f;
        }
        __syncthreads();
        const int kmin = s_kmin;

        // ---- scatter taps: dir=0 does center+down(5), dir=1 does up(5) ----
        if (id >= 0) {
            const float E1 = 0.36787944117144233f;
            if (dir == 0) {
                int rel = r0v - kmin;
                if (rel < 16) As[rel][el] = vc;
                float ratio = __expf(-f - 0.5f), v = vc;
#pragma unroll
                for (int j = 1; j <= 5; ++j) {
                    v *= ratio; ratio *= E1;
                    int r = r0v - j;
                    if (r >= 0) {
                        int rel2 = r - kmin;
                        if (rel2 >= 0 && rel2 < 16) As[rel2][el] = v;
                    }
                }
            } else {
                float ratio = __expf(f - 0.5f), v = vc;
#pragma unroll
                for (int j = 1; j <= 5; ++j) {
                    v *= ratio; ratio *= E1;
                    int r = r0v + j;
                    if (r < 128) {
                        int rel2 = r - kmin;
                        if (rel2 < 16) As[rel2][el] = v;
                    }
                }
            }
        }
        // ---- fill B slice (16 k-rows x 128 cols) ----
        for (int i = tid * 4; i < 16 * 128; i += 1024) {
            int k = i >> 7, n = i & 127;
            int gk = kmin + k, gn = n0 + n;
            float4 w = make_float4(0.f, 0.f, 0.f, 0.f);
            if (gk < 128 && gn < NCAT) w = *(const float4*)&g_Wcat[gk * NCAT + gn];
            *(float4*)&Bs[k][n] = w;
        }
        __syncthreads();

        // ---- 16-step k-loop ----
        unsigned long long acc[8][4];
#pragma unroll
        for (int i = 0; i < 8; ++i)
#pragma unroll
            for (int j = 0; j < 4; ++j) acc[i][j] = 0ull;
#pragma unroll
        for (int kk = 0; kk < 16; ++kk) {
            float4 a0 = *(const float4*)&As[kk][ty * 8];
            float4 a1 = *(const float4*)&As[kk][ty * 8 + 4];
            F4U b0, b1;
            b0.f = *(const float4*)&Bs[kk][tx * 8];
            b1.f = *(const float4*)&Bs[kk][tx * 8 + 4];
            unsigned long long bb[4] = {b0.u[0], b0.u[1], b1.u[0], b1.u[1]};
            float av[8] = {a0.x, a0.y, a0.z, a0.w, a1.x, a1.y, a1.z, a1.w};
#pragma unroll
            for (int i = 0; i < 8; ++i) {
                unsigned long long a2 = pack2(av[i], av[i]);
#pragma unroll
                for (int j = 0; j < 4; ++j) ffma2(acc[i][j], a2, bb[j]);
            }
        }

        // ---- epilogue ----
        const int nb = n0 + tx * 8;
        if (nb < NCAT) {
#pragma unroll
            for (int i = 0; i < 8; ++i) {
                int id2 = g_order[e0 + ty * 8 + i];
                if (id2 < 0) continue;
                float v[8];
#pragma unroll
                for (int j = 0; j < 4; ++j) {
                    v[2 * j]     = __uint_as_float((unsigned)(acc[i][j] & 0xffffffffull));
                    v[2 * j + 1] = __uint_as_float((unsigned)(acc[i][j] >> 32));
                }
                if (nb >= 160) {
                    int j2 = nb - 160;
                    int si = eis[id2], ti = eit[id2];
                    const float* hw1 = g_hW + (size_t)si * EMB_EDGE + j2;
                    const float* hw2 = g_hW + (size_t)A_NUM * EMB_EDGE
                                       + (size_t)ti * EMB_EDGE + j2;
                    float4 p1a = *(const float4*)hw1, p1b = *(const float4*)(hw1 + 4);
                    float4 p2a = *(const float4*)hw2, p2b = *(const float4*)(hw2 + 4);
                    float add[8] = {p1a.x + p2a.x, p1a.y + p2a.y, p1a.z + p2a.z,
                                    p1a.w + p2a.w, p1b.x + p2b.x, p1b.y + p2b.y,
                                    p1b.z + p2b.z, p1b.w + p2b.w};
                    float r[8];
#pragma unroll
                    for (int j = 0; j < 8; ++j) {
                        float x = v[j] + add[j];
                        r[j] = x * (1.0f / 0.6f) / (1.0f + __expf(-x));
                    }
                    float* dst = out + OFF_M + (size_t)id2 * EMB_EDGE + j2;
                    *(float4*)dst       = make_float4(r[0], r[1], r[2], r[3]);
                    *(float4*)(dst + 4) = make_float4(r[4], r[5], r[6], r[7]);
                } else if (nb >= 48) {
                    float* dst = g_radW1 + (size_t)id2 * 112 + (nb - 48);
                    *(float4*)dst       = make_float4(v[0], v[1], v[2], v[3]);
                    *(float4*)(dst + 4) = make_float4(v[4], v[5], v[6], v[7]);
                } else {
                    int seg = nb >> 4;
                    size_t base = (seg == 0) ? OFF_RE2E : (seg == 1) ? OFF_AT : OFF_OUT;
                    float* dst = out + base + (size_t)id2 * 16 + (nb & 15);
                    *(float4*)dst       = make_float4(v[0], v[1], v[2], v[3]);
                    *(float4*)(dst + 4) = make_float4(v[4], v[5], v[6], v[7]);
                }
            }
        }
        __syncthreads();
    }
}

// ---------------- kernel 4: triplets ----------------
__global__ void __launch_bounds__(256)
trip_kernel(const int* __restrict__ tin, const int* __restrict__ tout,
            const float* __restrict__ vec, float* __restrict__ out) {
    int gidx = blockIdx.x * blockDim.x + threadIdx.x;
    int t = gidx >> 4;
    int c = gidx & 15;
    if (t >= T_N) return;
    int lane = threadIdx.x & 31;

    int i_out = 0;
    float cosv = 0.f;
    if ((lane & 15) == 0) {
        int i_in = tin[t];
        i_out = tout[t];
        float ax = vec[3 * (size_t)i_out + 0], ay = vec[3 * (size_t)i_out + 1],
              az = vec[3 * (size_t)i_out + 2];
        float bx = vec[3 * (size_t)i_in + 0], by = vec[3 * (size_t)i_in + 1],
              bz = vec[3 * (size_t)i_in + 2];
        cosv = ax * bx + ay * by + az * bz;
        cosv = fminf(1.f, fmaxf(-1.f, cosv));
    }
    const unsigned mask = 0xffffffffu;
    i_out = __shfl_sync(mask, i_out, lane & 16, 32);
    cosv  = __shfl_sync(mask, cosv, lane & 16, 32);

    const float* row = g_radW1 + (size_t)i_out * 112 + c;
    float x = cosv;
    float P0 = 1.f, P1 = x;
    float P2 = (3.f * x * P1 - 1.f * P0) * (1.f / 2.f);
    float P3 = (5.f * x * P2 - 2.f * P1) * (1.f / 3.f);
    float P4 = (7.f * x * P3 - 3.f * P2) * (1.f / 4.f);
    float P5 = (9.f * x * P4 - 4.f * P3) * (1.f / 5.f);
    float P6 = (11.f * x * P5 - 5.f * P4) * (1.f / 6.f);

    float acc;
    acc  = 0.28209479177387814f * P0 * row[0];
    acc += 0.4886025119029199f  * P1 * row[16];
    acc += 0.6307831305050401f  * P2 * row[32];
    acc += 0.7463526651802308f  * P3 * row[48];
    acc += 0.8462843753216345f  * P4 * row[64];
    acc += 0.9356025796273889f  * P5 * row[80];
    acc += 1.0171072362820548f  * P6 * row[96];

    out[OFF_CIR + (size_t)t * 16 + c] = acc;
}

// ---------------- launch ----------------
extern "C" void kernel_launch(void* const* d_in, const int* in_sizes, int n_in,
                              void* d_out, int out_size) {
    const float* h    = (const float*)d_in[0];
    const float* dist = (const float*)d_in[1];
    const float* vec  = (const float*)d_in[2];
    const int*   eis  = (const int*)d_in[3];
    const int*   eit  = (const int*)d_in[4];
    const int*   tin  = (const int*)d_in[5];
    const int*   tout = (const int*)d_in[6];
    const float* Wt   = (const float*)d_in[7];
    const float* Wc   = (const float*)d_in[8];
    const float* Wh   = (const float*)d_in[9];
    const float* Wo   = (const float*)d_in[10];
    const float* We   = (const float*)d_in[11];
    float* out = (float*)d_out;

    k_init<<<(128 * NCAT + 255) / 256, 256>>>(Wt, Wc, Wh, Wo, We);
    k_gemm_hist<<<GEMM_BLKS + HIST_BLKS, 256>>>(h, We, dist);
    k_scatter<<<(E_N + 1023) / 1024, 256>>>(dist);
    main_band<<<6 * NSL, 256>>>(dist, eis, eit, out);
    trip_kernel<<<(T_N * 16) / 256, 256>>>(tin, tout, vec, out);
}

// round 7
// speedup vs baseline: 2.0683x; 1.1272x over previous
#include <cuda_runtime.h>
#include <cstdint>
#include <math.h>

#define E_N      200000
#define A_NUM    8000
#define T_N      1000000
#define NCAT     672
#define EMB_EDGE 512
#define N_TILES  1563
#define NSL      261          // slices; main grid = 6*NSL
#define L_TILES  6            // contiguous tiles per CTA

#define OFF_M    0ull
#define OFF_AT   102400000ull
#define OFF_OUT  105600000ull
#define OFF_RE2E 108800000ull
#define OFF_CIR  112000000ull

#define GEMM_BLKS 504
#define HIST_BLKS 128

__device__ float g_radW1[(size_t)E_N * 112];
__device__ float g_hW[2ull * A_NUM * EMB_EDGE];
__device__ float g_Wcat[128 * NCAT];            // [k][n]
__device__ int   g_cnt[128];
__device__ int   g_pos[128];
__device__ int   g_done;
__device__ int   g_order[N_TILES * 128];

// ---------------- helpers ----------------
__device__ __forceinline__ void ffma2(unsigned long long& d, unsigned long long a,
                                      unsigned long long b) {
    asm("fma.rn.f32x2 %0, %1, %2, %3;" : "=l"(d) : "l"(a), "l"(b), "l"(d));
}
__device__ __forceinline__ unsigned long long pack2(float x, float y) {
    unsigned long long r;
    asm("mov.b64 %0, {%1, %2};" : "=l"(r) : "f"(x), "f"(y));
    return r;
}
union F4U { float4 f; unsigned long long u[2]; };

__device__ __forceinline__ int edge_r0(float d) {
    float u = d * (127.0f / 12.0f);
    int r0 = __float2int_rn(u);
    return max(0, min(127, r0));
}

// ---------------- kernel 0: init + build wcat ----------------
__global__ void k_init(const float* __restrict__ Wt, const float* __restrict__ Wc,
                       const float* __restrict__ Wh, const float* __restrict__ Wo,
                       const float* __restrict__ We) {
    int i = blockIdx.x * blockDim.x + threadIdx.x;
    if (blockIdx.x == 0) {
        int tid = threadIdx.x;
        if (tid < 128) { g_cnt[tid] = 0; g_pos[tid] = 0; }
        if (tid == 128) g_done = 0;
        if (tid >= 129 && tid < 129 + (N_TILES * 128 - E_N))
            g_order[E_N + tid - 129] = -1;
    }
    if (i >= 128 * NCAT) return;
    int k = i / NCAT, n = i - k * NCAT;
    float v;
    if (n < 16)        v = Wt[k * 16 + n];
    else if (n < 32)   v = Wh[k * 16 + (n - 16)];
    else if (n < 48)   v = Wo[k * 16 + (n - 32)];
    else if (n < 160)  v = Wc[k * 112 + (n - 48)];
    else               v = We[(size_t)(512 + k) * EMB_EDGE + (n - 160)];
    g_Wcat[i] = v;
}

// ---------------- kernel 1: gemm_hw + histogram/scan ----------------
__global__ void __launch_bounds__(256, 2)
k_gemm_hist(const float* __restrict__ h, const float* __restrict__ We,
            const float* __restrict__ dist) {
    __shared__ float As[32][132];
    __shared__ float Bs[32][132];

    if (blockIdx.x >= GEMM_BLKS) {
        __shared__ int scnt[128];
        __shared__ int sv[128];
        __shared__ int sdone;
        const int hb = blockIdx.x - GEMM_BLKS;
        const int tid = threadIdx.x;
        if (tid < 128) scnt[tid] = 0;
        __syncthreads();
        for (int e = hb * 256 + tid; e < E_N; e += HIST_BLKS * 256)
            atomicAdd(&scnt[edge_r0(dist[e])], 1);
        __syncthreads();
        if (tid < 128 && scnt[tid] > 0) atomicAdd(&g_cnt[tid], scnt[tid]);
        __threadfence();
        if (tid == 0) {
            int o = atomicAdd(&g_done, 1);
            sdone = (o == HIST_BLKS - 1) ? 1 : 0;
        }
        __syncthreads();
        if (!sdone) return;
        int c0 = 0;
        if (tid < 128) { c0 = *((volatile int*)&g_cnt[tid]); sv[tid] = c0; }
        __syncthreads();
        for (int o = 1; o < 128; o <<= 1) {
            int v = 0;
            if (tid < 128 && tid >= o) v = sv[tid - o];
            __syncthreads();
            if (tid < 128) sv[tid] += v;
            __syncthreads();
        }
        if (tid < 128) g_pos[tid] = sv[tid] - c0;
        return;
    }

    const int bx = blockIdx.x;
    const int z = bx / 252;
    const int rem = bx % 252;
    const int by = rem / 4;
    const int bnx = rem % 4;
    const float* B = We + (size_t)z * 256 * EMB_EDGE;
    float* C = g_hW + (size_t)z * A_NUM * EMB_EDGE;
    const int m0 = by * 128;
    const int n0 = bnx * 128;
    const int tid = threadIdx.x;
    const int tx = tid & 15, ty = tid >> 4;

    unsigned long long acc[8][4];
#pragma unroll
    for (int i = 0; i < 8; ++i)
#pragma unroll
        for (int j = 0; j < 4; ++j) acc[i][j] = 0ull;

    for (int k0 = 0; k0 < 256; k0 += 32) {
        if (k0) __syncthreads();
#pragma unroll
        for (int i = tid; i < 128 * 32; i += 256) {
            int m = i >> 5, kk = i & 31;
            As[kk][m] = (m0 + m < A_NUM) ? h[(size_t)(m0 + m) * 256 + k0 + kk] : 0.f;
        }
#pragma unroll
        for (int i = tid * 4; i < 32 * 128; i += 1024) {
            int kk = i >> 7, n = i & 127;
            *(float4*)&Bs[kk][n] = *(const float4*)&B[(size_t)(k0 + kk) * EMB_EDGE + n0 + n];
        }
        __syncthreads();
#pragma unroll
        for (int kk = 0; kk < 32; ++kk) {
            float4 a0 = *(const float4*)&As[kk][ty * 8];
            float4 a1 = *(const float4*)&As[kk][ty * 8 + 4];
            F4U b0, b1;
            b0.f = *(const float4*)&Bs[kk][tx * 8];
            b1.f = *(const float4*)&Bs[kk][tx * 8 + 4];
            unsigned long long bb[4] = {b0.u[0], b0.u[1], b1.u[0], b1.u[1]};
            float av[8] = {a0.x, a0.y, a0.z, a0.w, a1.x, a1.y, a1.z, a1.w};
#pragma unroll
            for (int i = 0; i < 8; ++i) {
                unsigned long long a2 = pack2(av[i], av[i]);
#pragma unroll
                for (int j = 0; j < 4; ++j) ffma2(acc[i][j], a2, bb[j]);
            }
        }
    }
#pragma unroll
    for (int i = 0; i < 8; ++i) {
        int m = m0 + ty * 8 + i;
        if (m >= A_NUM) continue;
        float v[8];
#pragma unroll
        for (int j = 0; j < 4; ++j) {
            v[2 * j]     = __uint_as_float((unsigned)(acc[i][j] & 0xffffffffull));
            v[2 * j + 1] = __uint_as_float((unsigned)(acc[i][j] >> 32));
        }
        float* dst = C + (size_t)m * EMB_EDGE + n0 + tx * 8;
        *(float4*)dst       = make_float4(v[0], v[1], v[2], v[3]);
        *(float4*)(dst + 4) = make_float4(v[4], v[5], v[6], v[7]);
    }
}

// ---------------- kernel 2: scatter ----------------
__global__ void __launch_bounds__(256)
k_scatter(const float* __restrict__ dist) {
    __shared__ int scnt[128];
    __shared__ int sbase[128];
    const int tid = threadIdx.x;
    const int base = blockIdx.x * 1024;
    if (tid < 128) scnt[tid] = 0;
    __syncthreads();
    int r0[4], lp[4];
#pragma unroll
    for (int j = 0; j < 4; ++j) {
        int e = base + j * 256 + tid;
        r0[j] = -1;
        if (e < E_N) { r0[j] = edge_r0(dist[e]); lp[j] = atomicAdd(&scnt[r0[j]], 1); }
    }
    __syncthreads();
    if (tid < 128 && scnt[tid] > 0) sbase[tid] = atomicAdd(&g_pos[tid], scnt[tid]);
    __syncthreads();
#pragma unroll
    for (int j = 0; j < 4; ++j) {
        int e = base + j * 256 + tid;
        if (e < E_N) g_order[sbase[r0[j]] + lp[j]] = e;
    }
}

// ---------------- kernel 3: banded GEMM, 512 threads, 4x8 thread tile ------
__global__ void __launch_bounds__(512, 2)
main_band(const float* __restrict__ dist, const int* __restrict__ eis,
          const int* __restrict__ eit, float* __restrict__ out) {
    __shared__ float As[2][16][132];
    __shared__ float Bs[16][132];

    const int ci = blockIdx.x % 6;
    const int slice = blockIdx.x / 6;
    const int n0 = ci * 128;
    const int tid = threadIdx.x;
    const int tx = tid & 15, ty = tid >> 4;   // ty 0..31; rows ty*4+i
    const int t0 = slice * L_TILES;
    const int t1 = min(t0 + L_TILES, N_TILES);

    int kmin_prev = -1;
    int buf = 0;
    const float E1 = 0.36787944117144233f;   // exp(-1)

    for (int t = t0; t < t1; ++t, buf ^= 1) {
        const int e0 = t * 128;

        // ---- kmin from first (sorted) edge: broadcast loads, no reduction ----
        const int id0 = g_order[e0];
        const int kmin = max(0, edge_r0(dist[id0]) - 5);

        // ---- B slice fill only when band moved (uniform condition) ----
        if (kmin != kmin_prev) {
            __syncthreads();    // prior k-loop readers of Bs must be done
            if (tid >= 256) {
                int s = tid - 256;
#pragma unroll
                for (int q = 0; q < 2; ++q) {
                    int slot = s * 2 + q;
                    int k = slot >> 5;
                    int n = (slot & 31) * 4;
                    int gk = kmin + k, gn = n0 + n;
                    float4 w = make_float4(0.f, 0.f, 0.f, 0.f);
                    if (gk < 128 && gn < NCAT)
                        w = *(const float4*)&g_Wcat[gk * NCAT + gn];
                    *(float4*)&Bs[k][n] = w;
                }
            }
            kmin_prev = kmin;
        }

        // ---- A build: threads 0..255 write full columns (no zero pass) ----
        if (tid < 256) {
            const int el = tid & 127, dir = tid >> 7;
            const int id = g_order[e0 + el];
            float f = 0.f, vc = 0.f;
            int r0v = kmin;
            if (id >= 0) {
                float ds = dist[id] * (1.0f / 12.0f);
                float ds2 = ds * ds, ds5 = ds2 * ds2 * ds;
                float env = (ds < 1.f) ? (1.f + ds5 * (-21.f + ds * (35.f - 15.f * ds))) : 0.f;
                float u = ds * 127.f;
                r0v = __float2int_rn(u);
                r0v = max(0, min(127, r0v));
                f = u - (float)r0v;
                vc = env * expf(-0.5f * f * f);
            }
            const int center = r0v - kmin;   // 0..6 by construction
            if (dir == 0) {
                float v = vc;
                As[buf][center][el] = v;
                float ratio = __expf(-f - 0.5f);
                for (int rel = center - 1; rel >= 0; --rel) {
                    v *= ratio; ratio *= E1;
                    As[buf][rel][el] = v;
                }
            } else {
                float ratio = __expf(f - 0.5f);
                float v = vc;
                for (int rel = center + 1; rel < 16; ++rel) {
                    v *= ratio; ratio *= E1;
                    As[buf][rel][el] = v;
                }
            }
        }
        __syncthreads();

        // ---- 16-step k-loop, 4x8 thread tile ----
        unsigned long long acc[4][4];
#pragma unroll
        for (int i = 0; i < 4; ++i)
#pragma unroll
            for (int j = 0; j < 4; ++j) acc[i][j] = 0ull;
#pragma unroll
        for (int kk = 0; kk < 16; ++kk) {
            float4 a = *(const float4*)&As[buf][kk][ty * 4];
            F4U b0, b1;
            b0.f = *(const float4*)&Bs[kk][tx * 8];
            b1.f = *(const float4*)&Bs[kk][tx * 8 + 4];
            unsigned long long bb[4] = {b0.u[0], b0.u[1], b1.u[0], b1.u[1]};
            float av[4] = {a.x, a.y, a.z, a.w};
#pragma unroll
            for (int i = 0; i < 4; ++i) {
                unsigned long long a2 = pack2(av[i], av[i]);
#pragma unroll
                for (int j = 0; j < 4; ++j) ffma2(acc[i][j], a2, bb[j]);
            }
        }

        // ---- epilogue ----
        const int nb = n0 + tx * 8;
        if (nb < NCAT) {
#pragma unroll
            for (int i = 0; i < 4; ++i) {
                int id2 = g_order[e0 + ty * 4 + i];
                if (id2 < 0) continue;
                float v[8];
#pragma unroll
                for (int j = 0; j < 4; ++j) {
                    v[2 * j]     = __uint_as_float((unsigned)(acc[i][j] & 0xffffffffull));
                    v[2 * j + 1] = __uint_as_float((unsigned)(acc[i][j] >> 32));
                }
                if (nb >= 160) {
                    int j2 = nb - 160;
                    int si = eis[id2], ti = eit[id2];
                    const float* hw1 = g_hW + (size_t)si * EMB_EDGE + j2;
                    const float* hw2 = g_hW + (size_t)A_NUM * EMB_EDGE
                                       + (size_t)ti * EMB_EDGE + j2;
                    float* dst = out + OFF_M + (size_t)id2 * EMB_EDGE + j2;
#pragma unroll
                    for (int q = 0; q < 2; ++q) {
                        float4 a4 = *(const float4*)(hw1 + q * 4);
                        float4 b4 = *(const float4*)(hw2 + q * 4);
                        float x0 = v[q * 4 + 0] + a4.x + b4.x;
                        float x1 = v[q * 4 + 1] + a4.y + b4.y;
                        float x2 = v[q * 4 + 2] + a4.z + b4.z;
                        float x3 = v[q * 4 + 3] + a4.w + b4.w;
                        float4 o;
                        o.x = x0 * (1.0f / 0.6f) / (1.0f + __expf(-x0));
                        o.y = x1 * (1.0f / 0.6f) / (1.0f + __expf(-x1));
                        o.z = x2 * (1.0f / 0.6f) / (1.0f + __expf(-x2));
                        o.w = x3 * (1.0f / 0.6f) / (1.0f + __expf(-x3));
                        *(float4*)(dst + q * 4) = o;
                    }
                } else if (nb >= 48) {
                    float* dst = g_radW1 + (size_t)id2 * 112 + (nb - 48);
                    *(float4*)dst       = make_float4(v[0], v[1], v[2], v[3]);
                    *(float4*)(dst + 4) = make_float4(v[4], v[5], v[6], v[7]);
                } else {
                    int seg = nb >> 4;
                    size_t base = (seg == 0) ? OFF_RE2E : (seg == 1) ? OFF_AT : OFF_OUT;
                    float* dst = out + base + (size_t)id2 * 16 + (nb & 15);
                    *(float4*)dst       = make_float4(v[0], v[1], v[2], v[3]);
                    *(float4*)(dst + 4) = make_float4(v[4], v[5], v[6], v[7]);
                }
            }
        }
    }
}

// ---------------- kernel 4: triplets ----------------
__global__ void __launch_bounds__(256)
trip_kernel(const int* __restrict__ tin, const int* __restrict__ tout,
            const float* __restrict__ vec, float* __restrict__ out) {
    int gidx = blockIdx.x * blockDim.x + threadIdx.x;
    int t = gidx >> 4;
    int c = gidx & 15;
    if (t >= T_N) return;
    int lane = threadIdx.x & 31;

    int i_out = 0;
    float cosv = 0.f;
    if ((lane & 15) == 0) {
        int i_in = tin[t];
        i_out = tout[t];
        float ax = vec[3 * (size_t)i_out + 0], ay = vec[3 * (size_t)i_out + 1],
              az = vec[3 * (size_t)i_out + 2];
        float bx = vec[3 * (size_t)i_in + 0], by = vec[3 * (size_t)i_in + 1],
              bz = vec[3 * (size_t)i_in + 2];
        cosv = ax * bx + ay * by + az * bz;
        cosv = fminf(1.f, fmaxf(-1.f, cosv));
    }
    const unsigned mask = 0xffffffffu;
    i_out = __shfl_sync(mask, i_out, lane & 16, 32);
    cosv  = __shfl_sync(mask, cosv, lane & 16, 32);

    const float* row = g_radW1 + (size_t)i_out * 112 + c;
    float x = cosv;
    float P0 = 1.f, P1 = x;
    float P2 = (3.f * x * P1 - 1.f * P0) * (1.f / 2.f);
    float P3 = (5.f * x * P2 - 2.f * P1) * (1.f / 3.f);
    float P4 = (7.f * x * P3 - 3.f * P2) * (1.f / 4.f);
    float P5 = (9.f * x * P4 - 4.f * P3) * (1.f / 5.f);
    float P6 = (11.f * x * P5 - 5.f * P4) * (1.f / 6.f);

    float acc;
    acc  = 0.28209479177387814f * P0 * row[0];
    acc += 0.4886025119029199f  * P1 * row[16];
    acc += 0.6307831305050401f  * P2 * row[32];
    acc += 0.7463526651802308f  * P3 * row[48];
    acc += 0.8462843753216345f  * P4 * row[64];
    acc += 0.9356025796273889f  * P5 * row[80];
    acc += 1.0171072362820548f  * P6 * row[96];

    out[OFF_CIR + (size_t)t * 16 + c] = acc;
}

// ---------------- launch ----------------
extern "C" void kernel_launch(void* const* d_in, const int* in_sizes, int n_in,
                              void* d_out, int out_size) {
    const float* h    = (const float*)d_in[0];
    const float* dist = (const float*)d_in[1];
    const float* vec  = (const float*)d_in[2];
    const int*   eis  = (const int*)d_in[3];
    const int*   eit  = (const int*)d_in[4];
    const int*   tin  = (const int*)d_in[5];
    const int*   tout = (const int*)d_in[6];
    const float* Wt   = (const float*)d_in[7];
    const float* Wc   = (const float*)d_in[8];
    const float* Wh   = (const float*)d_in[9];
    const float* Wo   = (const float*)d_in[10];
    const float* We   = (const float*)d_in[11];
    float* out = (float*)d_out;

    k_init<<<(128 * NCAT + 255) / 256, 256>>>(Wt, Wc, Wh, Wo, We);
    k_gemm_hist<<<GEMM_BLKS + HIST_BLKS, 256>>>(h, We, dist);
    k_scatter<<<(E_N + 1023) / 1024, 256>>>(dist);
    main_band<<<6 * NSL, 512>>>(dist, eis, eit, out);
    trip_kernel<<<(T_N * 16) / 256, 256>>>(tin, tout, vec, out);
}